// round 1
// baseline (speedup 1.0000x reference)
#include <cuda_runtime.h>
#include <cuda_bf16.h>
#include <math.h>

#define NN 50000
#define NE 500000
#define HIDF 256
#define NEG_SLOPE 0.2f

// ---------------- scratch (no allocation allowed) ----------------
__device__ __align__(256) float g_bufA[(size_t)NN * HIDF];
__device__ __align__(256) float g_bufB[(size_t)NN * HIDF];
__device__ __align__(256) float g_bufC[(size_t)NN * HIDF];
__device__ int g_src[NE];
__device__ int g_dst[NE];
__device__ int g_cnt[NN];
__device__ int g_rowptr[NN + 1];
__device__ int g_cursor[NN];
__device__ int g_ids[NE];
__device__ float g_as[NN];
__device__ float g_ad[NN];
__device__ int g_is64;

// ---------------- helpers ----------------
__device__ __forceinline__ float lrelu(float e) { return e > 0.f ? e : NEG_SLOPE * e; }

// ---------------- edge index dtype detection ----------------
// If edge_index is int64, every odd 32-bit word among the first 1e6 words is a
// zero high-half (values < 50000). If int32, odd words are ~uniform node ids.
__global__ void detect_kernel(const int* __restrict__ w) {
    __shared__ int sh[256];
    int nz = 0;
    for (int i = 1 + 2 * (int)threadIdx.x; i < 1000000; i += 2 * (int)blockDim.x)
        nz += (w[i] != 0);
    sh[threadIdx.x] = nz;
    __syncthreads();
    for (int off = 128; off; off >>= 1) {
        if ((int)threadIdx.x < off) sh[threadIdx.x] += sh[threadIdx.x + off];
        __syncthreads();
    }
    if (threadIdx.x == 0) g_is64 = (sh[0] == 0) ? 1 : 0;
}

__global__ void convert_kernel(const void* __restrict__ ei) {
    int e = blockIdx.x * blockDim.x + threadIdx.x;
    if (e >= NE) return;
    if (g_is64) {
        const long long* p = (const long long*)ei;
        g_src[e] = (int)p[e];
        g_dst[e] = (int)p[NE + e];
    } else {
        const int* p = (const int*)ei;
        g_src[e] = p[e];
        g_dst[e] = p[NE + e];
    }
}

// ---------------- CSR build (sorted by dst) ----------------
__global__ void zero_cnt_kernel() {
    int i = blockIdx.x * blockDim.x + threadIdx.x;
    if (i < NN) g_cnt[i] = 0;
}

__global__ void count_kernel() {
    int e = blockIdx.x * blockDim.x + threadIdx.x;
    if (e < NE) atomicAdd(&g_cnt[g_dst[e]], 1);
}

__global__ void scan_kernel() {
    __shared__ int sdata[1024];
    __shared__ int base_s;
    if (threadIdx.x == 0) base_s = 0;
    __syncthreads();
    for (int start = 0; start < NN; start += 1024) {
        int i = start + (int)threadIdx.x;
        int v = (i < NN) ? g_cnt[i] : 0;
        sdata[threadIdx.x] = v;
        __syncthreads();
        for (int off = 1; off < 1024; off <<= 1) {
            int t = ((int)threadIdx.x >= off) ? sdata[threadIdx.x - off] : 0;
            __syncthreads();
            sdata[threadIdx.x] += t;
            __syncthreads();
        }
        int incl = sdata[threadIdx.x];
        int total = sdata[1023];
        int base = base_s;
        if (i < NN) g_rowptr[i] = base + incl - v;
        __syncthreads();
        if (threadIdx.x == 0) base_s = base + total;
        __syncthreads();
    }
    if (threadIdx.x == 0) g_rowptr[NN] = base_s;
}

__global__ void cursor_kernel() {
    int i = blockIdx.x * blockDim.x + threadIdx.x;
    if (i < NN) g_cursor[i] = g_rowptr[i];
}

__global__ void fill_kernel() {
    int e = blockIdx.x * blockDim.x + threadIdx.x;
    if (e < NE) {
        int pos = atomicAdd(&g_cursor[g_dst[e]], 1);
        g_ids[pos] = e;
    }
}

// ---------------- SGEMM: C[M,256] = A[M,K] @ B[K,256] (row-major) ----------------
#define BM 128
#define BN 128
#define BKK 16
#define TM 8
#define TN 8

__global__ __launch_bounds__(256) void sgemm_kernel(const float* __restrict__ A,
                                                    const float* __restrict__ B,
                                                    float* __restrict__ C,
                                                    int M, int K) {
    __shared__ float As[BKK][BM];
    __shared__ float Bs[BKK][BN];
    const int tid = threadIdx.x;
    const int rowTile = blockIdx.y;
    const int colTile = blockIdx.x;
    const int innerRowA = tid >> 2;         // 0..63
    const int innerColA = (tid & 3) << 2;   // 0,4,8,12
    const int innerRowB = tid >> 5;         // 0..7
    const int innerColB = (tid & 31) << 2;  // 0..124
    const int threadRow = tid >> 4;         // 0..15
    const int threadCol = tid & 15;         // 0..15

    float acc[TM][TN];
#pragma unroll
    for (int i = 0; i < TM; i++)
#pragma unroll
        for (int j = 0; j < TN; j++) acc[i][j] = 0.f;
    float regM[TM], regN[TN];

    for (int k0 = 0; k0 < K; k0 += BKK) {
#pragma unroll
        for (int r = 0; r < 2; r++) {
            int arow = innerRowA + r * 64;
            int grow = rowTile * BM + arow;
            float4 v = make_float4(0.f, 0.f, 0.f, 0.f);
            if (grow < M) v = *(const float4*)(A + (size_t)grow * K + k0 + innerColA);
            As[innerColA + 0][arow] = v.x;
            As[innerColA + 1][arow] = v.y;
            As[innerColA + 2][arow] = v.z;
            As[innerColA + 3][arow] = v.w;
        }
#pragma unroll
        for (int r = 0; r < 2; r++) {
            int brow = innerRowB + r * 8;
            float4 v = *(const float4*)(B + (size_t)(k0 + brow) * 256 + colTile * BN + innerColB);
            *(float4*)&Bs[brow][innerColB] = v;
        }
        __syncthreads();
#pragma unroll
        for (int k = 0; k < BKK; k++) {
#pragma unroll
            for (int i = 0; i < TM; i++) regM[i] = As[k][threadRow * TM + i];
#pragma unroll
            for (int j = 0; j < TN; j++) regN[j] = Bs[k][threadCol * TN + j];
#pragma unroll
            for (int i = 0; i < TM; i++)
#pragma unroll
                for (int j = 0; j < TN; j++) acc[i][j] += regM[i] * regN[j];
        }
        __syncthreads();
    }
#pragma unroll
    for (int i = 0; i < TM; i++) {
        int grow = rowTile * BM + threadRow * TM + i;
        if (grow >= M) continue;
        float* crow = C + (size_t)grow * 256 + colTile * BN + threadCol * TN;
        *(float4*)crow = make_float4(acc[i][0], acc[i][1], acc[i][2], acc[i][3]);
        *(float4*)(crow + 4) = make_float4(acc[i][4], acc[i][5], acc[i][6], acc[i][7]);
    }
}

// ---------------- per-node attention coefficients: as[n] = h[n].a_src, ad[n] = h[n].a_dst ----
__global__ void alphas_kernel(const float* __restrict__ h,
                              const float* __restrict__ avs,
                              const float* __restrict__ avd) {
    int node = blockIdx.x * (blockDim.x >> 5) + (threadIdx.x >> 5);
    int lane = threadIdx.x & 31;
    if (node >= NN) return;
    const float4* hr = (const float4*)(h + (size_t)node * HIDF);
    const float4* s4 = (const float4*)avs;
    const float4* d4 = (const float4*)avd;
    float ss = 0.f, sd = 0.f;
#pragma unroll
    for (int k = 0; k < 2; k++) {
        int c = lane + k * 32;
        float4 hv = hr[c];
        float4 a = s4[c];
        float4 b = d4[c];
        ss += hv.x * a.x + hv.y * a.y + hv.z * a.z + hv.w * a.w;
        sd += hv.x * b.x + hv.y * b.y + hv.z * b.z + hv.w * b.w;
    }
#pragma unroll
    for (int o = 16; o; o >>= 1) {
        ss += __shfl_xor_sync(0xffffffffu, ss, o);
        sd += __shfl_xor_sync(0xffffffffu, sd, o);
    }
    if (lane == 0) {
        g_as[node] = ss;
        g_ad[node] = sd;
    }
}

// ---------------- warp-per-node segment softmax + weighted aggregation ----------------
__global__ void aggregate_kernel(const float* __restrict__ h,
                                 const float* __restrict__ bias,
                                 float* __restrict__ out,
                                 int do_relu) {
    int node = blockIdx.x * (blockDim.x >> 5) + (threadIdx.x >> 5);
    int lane = threadIdx.x & 31;
    if (node >= NN) return;
    int beg = g_rowptr[node];
    int end = g_rowptr[node + 1];
    float add = g_ad[node];
    float e_self = lrelu(g_as[node] + add);

    // pass 1: max over edges + self loop
    float m = e_self;
    for (int j = beg + lane; j < end; j += 32) {
        int sj = g_src[g_ids[j]];
        m = fmaxf(m, lrelu(g_as[sj] + add));
    }
#pragma unroll
    for (int o = 16; o; o >>= 1) m = fmaxf(m, __shfl_xor_sync(0xffffffffu, m, o));

    // pass 2: exp-sum
    float s = 0.f;
    for (int j = beg + lane; j < end; j += 32) {
        int sj = g_src[g_ids[j]];
        s += __expf(lrelu(g_as[sj] + add) - m);
    }
#pragma unroll
    for (int o = 16; o; o >>= 1) s += __shfl_xor_sync(0xffffffffu, s, o);
    s += __expf(e_self - m);
    float inv = 1.0f / s;

    // pass 3: weighted feature accumulation (warp-wide over 256 cols)
    int c0 = lane;        // float4 index
    int c1 = lane + 32;   // float4 index
    float w = __expf(e_self - m) * inv;
    const float4* hp = (const float4*)(h + (size_t)node * HIDF);
    float4 v0 = hp[c0], v1 = hp[c1];
    float4 acc0 = make_float4(w * v0.x, w * v0.y, w * v0.z, w * v0.w);
    float4 acc1 = make_float4(w * v1.x, w * v1.y, w * v1.z, w * v1.w);
    for (int j = beg; j < end; j++) {
        int sj = g_src[g_ids[j]];
        float wj = __expf(lrelu(g_as[sj] + add) - m) * inv;
        const float4* hq = (const float4*)(h + (size_t)sj * HIDF);
        float4 u0 = hq[c0], u1 = hq[c1];
        acc0.x += wj * u0.x; acc0.y += wj * u0.y; acc0.z += wj * u0.z; acc0.w += wj * u0.w;
        acc1.x += wj * u1.x; acc1.y += wj * u1.y; acc1.z += wj * u1.z; acc1.w += wj * u1.w;
    }
    const float4* b4 = (const float4*)bias;
    float4 b0 = b4[c0], b1 = b4[c1];
    acc0.x += b0.x; acc0.y += b0.y; acc0.z += b0.z; acc0.w += b0.w;
    acc1.x += b1.x; acc1.y += b1.y; acc1.z += b1.z; acc1.w += b1.w;
    if (do_relu) {
        acc0.x = fmaxf(acc0.x, 0.f); acc0.y = fmaxf(acc0.y, 0.f);
        acc0.z = fmaxf(acc0.z, 0.f); acc0.w = fmaxf(acc0.w, 0.f);
        acc1.x = fmaxf(acc1.x, 0.f); acc1.y = fmaxf(acc1.y, 0.f);
        acc1.z = fmaxf(acc1.z, 0.f); acc1.w = fmaxf(acc1.w, 0.f);
    }
    float4* op = (float4*)(out + (size_t)node * HIDF);
    op[c0] = acc0;
    op[c1] = acc1;
}

// ---------------- edge head: out[e] = P1[src[e]] + P2[dst[e]] + lin_b ----------------
__global__ void edge_out_kernel(const float* __restrict__ P1,
                                const float* __restrict__ P2,
                                const float* __restrict__ lin_b,
                                float* __restrict__ out) {
    int e = blockIdx.x * (blockDim.x >> 5) + (threadIdx.x >> 5);
    int lane = threadIdx.x & 31;
    if (e >= NE) return;
    int s = g_src[e];
    int d = g_dst[e];
    const float4* p1 = (const float4*)(P1 + (size_t)s * HIDF);
    const float4* p2 = (const float4*)(P2 + (size_t)d * HIDF);
    const float4* b4 = (const float4*)lin_b;
    float4* o4 = (float4*)(out + (size_t)e * HIDF);
#pragma unroll
    for (int k = 0; k < 2; k++) {
        int c = lane + k * 32;
        float4 a = p1[c];
        float4 b = p2[c];
        float4 bb = b4[c];
        o4[c] = make_float4(a.x + b.x + bb.x, a.y + b.y + bb.y,
                            a.z + b.z + bb.z, a.w + b.w + bb.w);
    }
}

// ---------------- host ----------------
extern "C" void kernel_launch(void* const* d_in, const int* in_sizes, int n_in,
                              void* d_out, int out_size) {
    const float* x      = (const float*)d_in[0];
    const void*  eidx   = d_in[1];
    const float* W1     = (const float*)d_in[2];
    const float* a1_src = (const float*)d_in[3];
    const float* a1_dst = (const float*)d_in[4];
    const float* b1     = (const float*)d_in[5];
    const float* W2     = (const float*)d_in[6];
    const float* a2_src = (const float*)d_in[7];
    const float* a2_dst = (const float*)d_in[8];
    const float* b2     = (const float*)d_in[9];
    const float* lin_W  = (const float*)d_in[10];
    const float* lin_b  = (const float*)d_in[11];
    float* out = (float*)d_out;

    float *bufA, *bufB, *bufC;
    cudaGetSymbolAddress((void**)&bufA, g_bufA);
    cudaGetSymbolAddress((void**)&bufB, g_bufB);
    cudaGetSymbolAddress((void**)&bufC, g_bufC);

    const int TPB = 256;
    const int edgeBlocks = (NE + TPB - 1) / TPB;
    const int nodeBlocks = (NN + TPB - 1) / TPB;
    const int warpNodeBlocks = (NN + 7) / 8;   // 8 warps per block
    const int warpEdgeBlocks = (NE + 7) / 8;

    // --- normalize edge index + build CSR-by-dst ---
    detect_kernel<<<1, 256>>>((const int*)eidx);
    convert_kernel<<<edgeBlocks, TPB>>>(eidx);
    zero_cnt_kernel<<<nodeBlocks, TPB>>>();
    count_kernel<<<edgeBlocks, TPB>>>();
    scan_kernel<<<1, 1024>>>();
    cursor_kernel<<<nodeBlocks, TPB>>>();
    fill_kernel<<<edgeBlocks, TPB>>>();

    dim3 ggrid(2, (NN + BM - 1) / BM);

    // --- layer 1 ---
    sgemm_kernel<<<ggrid, 256>>>(x, W1, bufA, NN, 128);
    alphas_kernel<<<warpNodeBlocks, TPB>>>(bufA, a1_src, a1_dst);
    aggregate_kernel<<<warpNodeBlocks, TPB>>>(bufA, b1, bufB, 1);

    // --- layer 2 ---
    sgemm_kernel<<<ggrid, 256>>>(bufB, W2, bufC, NN, 256);
    alphas_kernel<<<warpNodeBlocks, TPB>>>(bufC, a2_src, a2_dst);
    aggregate_kernel<<<warpNodeBlocks, TPB>>>(bufC, b2, bufA, 0);

    // --- edge head: split lin_W into src/dst halves ---
    sgemm_kernel<<<ggrid, 256>>>(bufA, lin_W, bufB, NN, 256);                 // P1
    sgemm_kernel<<<ggrid, 256>>>(bufA, lin_W + 256 * 256, bufC, NN, 256);     // P2
    edge_out_kernel<<<warpEdgeBlocks, TPB>>>(bufB, bufC, lin_b, out);
}